// round 15
// baseline (speedup 1.0000x reference)
#include <cuda_runtime.h>
#include <cuda_fp16.h>
#include <math.h>
#include <stdint.h>

// ---------------- static problem config ----------------
#define BB      2
#define TT      8
#define HH      64
#define WW      64
#define CC      128
#define LL      (TT * HH * WW)      // 32768
#define NHEADS  4
#define HD      32
#define NN      512                  // tokens per window
#define QBLK    128                  // queries per CTA
#define KBLK    64                   // keys per iteration
#define NKB     (NN / KBLK)          // 8
#define SCALE_Q 0.17677669529663687f // 32^-0.5
#define LOG2E   1.4426950408889634f

#define QKV_ELEMS  (3 * BB * LL * CC)   // 25165824
#define WGT_ELEMS  (CC * 27)            // 3456
#define BIAS_ELEMS (CC)                 // 128

// fp16 scratch: [win(128)][head(4)] slabs
// Kh: [wh][n(512)][d(32)] row-major; Vh: [wh][d(32)][n(512)] (transposed)
#define WH_SLAB (512 * 32)
__device__ __half d_Kh[128 * 4 * WH_SLAB];
__device__ __half d_Vh[128 * 4 * WH_SLAB];
// LePE conv result, same layout as out (B, L, C) fp32
__device__ float d_conv[(size_t)BB * LL * CC];

// window l index: l = tB*8192 + ts*4096 + hs*64 + wB*4 + ws
__device__ __forceinline__ int l_of(int n, int tB, int wB) {
    return tB * 8192 + (n >> 8) * 4096 + ((n >> 2) & 63) * 64 + wB * 4 + (n & 3);
}

__device__ __forceinline__ void mma16816(float c[4], const unsigned a[4],
                                         unsigned b0, unsigned b1) {
    asm volatile(
        "mma.sync.aligned.m16n8k16.row.col.f32.f16.f16.f32 "
        "{%0,%1,%2,%3},{%4,%5,%6,%7},{%8,%9},{%0,%1,%2,%3};\n"
        : "+f"(c[0]), "+f"(c[1]), "+f"(c[2]), "+f"(c[3])
        : "r"(a[0]), "r"(a[1]), "r"(a[2]), "r"(a[3]), "r"(b0), "r"(b1));
}

__device__ __forceinline__ void ldsm4(unsigned& r0, unsigned& r1,
                                      unsigned& r2, unsigned& r3, uint32_t addr) {
    asm volatile(
        "ldmatrix.sync.aligned.m8n8.x4.shared.b16 {%0,%1,%2,%3}, [%4];\n"
        : "=r"(r0), "=r"(r1), "=r"(r2), "=r"(r3) : "r"(addr));
}

__device__ __forceinline__ unsigned pack_h2(float lo, float hi) {
    __half2 h = __floats2half2_rn(lo, hi);
    return *reinterpret_cast<unsigned*>(&h);
}

__device__ __forceinline__ float ex2(float x) {
    float y;
    asm("ex2.approx.f32 %0, %1;" : "=f"(y) : "f"(x));
    return y;
}

__device__ __forceinline__ void cp16(uint32_t dst, const void* src) {
    asm volatile("cp.async.cg.shared.global [%0], [%1], 16;\n" :: "r"(dst), "l"(src));
}
__device__ __forceinline__ void cp_commit() {
    asm volatile("cp.async.commit_group;\n" ::: "memory");
}
__device__ __forceinline__ void cp_wait1() {
    asm volatile("cp.async.wait_group 1;\n" ::: "memory");
}
__device__ __forceinline__ void cp_wait0() {
    asm volatile("cp.async.wait_group 0;\n" ::: "memory");
}

// ---------------- fused prepass: lepe conv (blocks 0..1023) + K/V reorg (1024..5119) ----
// Both parts are independent: lepe reads V plane -> d_conv; reorg reads K,V -> d_Kh/d_Vh.
__global__ __launch_bounds__(256)
void prepass_kernel(const float* __restrict__ qkv, const float* __restrict__ wgt,
                    const float* __restrict__ bias) {
    __shared__ __align__(16) float slab[NN * 16];
    __shared__ __align__(16) float wt[27][16];
    __shared__ __align__(16) float bs[16];

    const int tid = threadIdx.x;

    if (blockIdx.x >= 1024) {
        // ---------------- reorg part ----------------
        int gid  = (blockIdx.x - 1024) * 256 + tid;
        int dq   = gid & 3;
        int n    = (gid >> 2) & 511;
        int head = (gid >> 11) & 3;
        int win  = gid >> 13;

        int b  = win >> 6;
        int tB = (win >> 4) & 3;
        int wB = win & 15;
        int l  = l_of(n, tB, wB);

        const size_t plane = (size_t)BB * LL * CC;
        const float* kp = qkv + plane + ((size_t)b * LL + l) * CC + head * HD + dq * 8;
        const float* vp = kp + plane;

        size_t wh = (size_t)(win * 4 + head);
        __half* kd = d_Kh + wh * WH_SLAB + (size_t)n * 32 + dq * 8;
        __half* vd = d_Vh + wh * WH_SLAB + n;

        float4 k0 = ((const float4*)kp)[0];
        float4 k1 = ((const float4*)kp)[1];
        uint4 uk;
        ((__half2*)&uk)[0] = __floats2half2_rn(k0.x, k0.y);
        ((__half2*)&uk)[1] = __floats2half2_rn(k0.z, k0.w);
        ((__half2*)&uk)[2] = __floats2half2_rn(k1.x, k1.y);
        ((__half2*)&uk)[3] = __floats2half2_rn(k1.z, k1.w);
        *(uint4*)kd = uk;

        float4 v0 = ((const float4*)vp)[0];
        float4 v1 = ((const float4*)vp)[1];
        int d0 = dq * 8;
        vd[(size_t)(d0 + 0) * 512] = __float2half_rn(v0.x);
        vd[(size_t)(d0 + 1) * 512] = __float2half_rn(v0.y);
        vd[(size_t)(d0 + 2) * 512] = __float2half_rn(v0.z);
        vd[(size_t)(d0 + 3) * 512] = __float2half_rn(v0.w);
        vd[(size_t)(d0 + 4) * 512] = __float2half_rn(v1.x);
        vd[(size_t)(d0 + 5) * 512] = __float2half_rn(v1.y);
        vd[(size_t)(d0 + 6) * 512] = __float2half_rn(v1.z);
        vd[(size_t)(d0 + 7) * 512] = __float2half_rn(v1.w);
        return;
    }

    // ---------------- lepe part ----------------
    const int widx  = blockIdx.x >> 3;
    const int chunk = blockIdx.x & 7;
    const int c0    = chunk * 16;
    const int b  = widx >> 6;
    const int tB = (widx >> 4) & 3;
    const int wB = widx & 15;

    const float* vg = qkv + 2 * (size_t)BB * LL * CC + (size_t)b * LL * CC + c0;

    for (int t = tid; t < NN * 4; t += 256) {
        int n = t >> 2, cgq = t & 3;
        int l = l_of(n, tB, wB);
        float4 f = *(const float4*)(vg + (size_t)l * CC + cgq * 4);
        *(float4*)&slab[n * 16 + cgq * 4] = f;
    }
    for (int t = tid; t < 27 * 16; t += 256) {
        int tap = t >> 4, ci = t & 15;
        wt[tap][ci] = wgt[(size_t)(c0 + ci) * 27 + tap];
    }
    if (tid < 16) bs[tid] = bias[c0 + tid];
    __syncthreads();

    const int cg     = tid & 3;
    const int ws     = (tid >> 2) & 3;
    const int hstrip = (tid >> 4) & 15;
    const int hs0    = hstrip * 4;
    float4 bias4 = *(float4*)&bs[cg * 4];
    float* og = d_conv + (size_t)b * LL * CC + c0;

#pragma unroll
    for (int ts = 0; ts < 2; ts++) {
        float4 acc[4];
#pragma unroll
        for (int j = 0; j < 4; j++) acc[j] = bias4;

#pragma unroll
        for (int zt = 0; zt < 2; zt++) {
            const int dt1 = zt - ts + 1;
#pragma unroll
            for (int dw = -1; dw <= 1; dw++) {
                int zw = ws + dw;
                if ((unsigned)zw >= 4u) continue;
                float4 wm = *(float4*)&wt[dt1 * 9 + 0 * 3 + (dw + 1)][cg * 4];
                float4 wz = *(float4*)&wt[dt1 * 9 + 1 * 3 + (dw + 1)][cg * 4];
                float4 wp = *(float4*)&wt[dt1 * 9 + 2 * 3 + (dw + 1)][cg * 4];
#pragma unroll
                for (int u = 0; u < 6; u++) {
                    int zh = hs0 - 1 + u;
                    if ((unsigned)zh >= 64u) continue;
                    float4 v = *(float4*)&slab[(zt * 256 + zh * 4 + zw) * 16 + cg * 4];
                    if (u <= 3) {
                        acc[u].x += v.x * wm.x; acc[u].y += v.y * wm.y;
                        acc[u].z += v.z * wm.z; acc[u].w += v.w * wm.w;
                    }
                    if (u >= 1 && u <= 4) {
                        acc[u-1].x += v.x * wz.x; acc[u-1].y += v.y * wz.y;
                        acc[u-1].z += v.z * wz.z; acc[u-1].w += v.w * wz.w;
                    }
                    if (u >= 2) {
                        acc[u-2].x += v.x * wp.x; acc[u-2].y += v.y * wp.y;
                        acc[u-2].z += v.z * wp.z; acc[u-2].w += v.w * wp.w;
                    }
                }
            }
        }

#pragma unroll
        for (int j = 0; j < 4; j++) {
            int n = ts * 256 + (hs0 + j) * 4 + ws;
            int l = l_of(n, tB, wB);
            *(float4*)(og + (size_t)l * CC + cg * 4) = acc[j];
        }
    }
}

// ---------------- attention kernel: LDSM fragments + 3-stage cp.async ----------------
// grid = 2048 CTAs, 256 threads (8 warps x 16 q rows). Epilogue adds d_conv (prefetched).
__global__ __launch_bounds__(256, 2)
void attn_kernel(const float* __restrict__ qkv, float* __restrict__ out) {
    __shared__ __align__(16) __half Qs[QBLK][40];
    __shared__ __align__(16) __half Ks[3][KBLK][40];     // row stride 80B
    __shared__ __align__(16) __half Vt[3][HD][KBLK + 8]; // row stride 144B

    const int bid  = blockIdx.x;
    const int qb   = bid & 3;
    const int head = (bid >> 2) & 3;
    const int win  = bid >> 4;
    const int b    = win >> 6;
    const int tB   = (win >> 4) & 3;
    const int wB   = win & 15;

    const int tid  = threadIdx.x;
    const int warp = tid >> 5;
    const int lane = tid & 31;
    const int g    = lane >> 2;
    const int tg   = lane & 3;

    size_t wh = (size_t)(win * 4 + head);
    const __half* Kg = d_Kh + wh * WH_SLAB;
    const __half* Vg = d_Vh + wh * WH_SLAB;

    const uint32_t sK = (uint32_t)__cvta_generic_to_shared(&Ks[0][0][0]);
    const uint32_t sV = (uint32_t)__cvta_generic_to_shared(&Vt[0][0][0]);

    const int krow = tid >> 2, kpart = tid & 3;
    const int vrow = tid >> 3, vpart = tid & 7;
    const uint32_t kdstb = sK + (uint32_t)(krow * 80 + kpart * 16);
    const uint32_t vdstb = sV + (uint32_t)(vrow * 144 + vpart * 16);
    const __half* ksrc = Kg + (size_t)krow * 32 + kpart * 8;
    const __half* vsrc = Vg + (size_t)vrow * 512 + vpart * 8;

    // ---- prologue: issue kv stage0, stage1 ----
    cp16(kdstb, ksrc);
    cp16(vdstb, vsrc);
    cp_commit();
    cp16(kdstb + KBLK * 80, ksrc + 64 * 32);
    cp16(vdstb + HD * 144, vsrc + 64);
    cp_commit();

    // ---- epilogue indices + conv prefetch into registers (hidden by mainloop) ----
    const int rb = warp * 16;
    int n_lo = qb * QBLK + rb + g;
    int ll_lo = l_of(n_lo, tB, wB);
    int ll_hi = l_of(n_lo + 8, tB, wB);
    const float* cvg = d_conv + (size_t)b * LL * CC + head * HD;
    float2 cpre_lo[4], cpre_hi[4];
#pragma unroll
    for (int nt2 = 0; nt2 < 4; nt2++) {
        int col = nt2 * 8 + 2 * tg;
        cpre_lo[nt2] = *(const float2*)(cvg + (size_t)ll_lo * CC + col);
        cpre_hi[nt2] = *(const float2*)(cvg + (size_t)ll_hi * CC + col);
    }

    // ---- Q: fp32 direct load + scale + convert (overlaps with cp.async) ----
    const float QS = SCALE_Q * LOG2E;
    const float* qg = qkv + (size_t)b * LL * CC + head * HD;
    for (int t = tid; t < QBLK * 8; t += 256) {
        int r = t >> 3, d4 = (t & 7) * 4;
        int n = qb * QBLK + r;
        int l = l_of(n, tB, wB);
        float4 f = *(const float4*)(qg + (size_t)l * CC + d4);
        *(__half2*)&Qs[r][d4]     = __floats2half2_rn(f.x * QS, f.y * QS);
        *(__half2*)&Qs[r][d4 + 2] = __floats2half2_rn(f.z * QS, f.w * QS);
    }
    __syncthreads();

    unsigned qa[2][4];
#pragma unroll
    for (int kk = 0; kk < 2; kk++) {
        qa[kk][0] = *(const unsigned*)&Qs[rb + g][kk * 16 + 2 * tg];
        qa[kk][1] = *(const unsigned*)&Qs[rb + g + 8][kk * 16 + 2 * tg];
        qa[kk][2] = *(const unsigned*)&Qs[rb + g][kk * 16 + 2 * tg + 8];
        qa[kk][3] = *(const unsigned*)&Qs[rb + g + 8][kk * 16 + 2 * tg + 8];
    }

    // ldmatrix lane addresses (stage 0 base): 8 rows per tile, 4 k/n-chunks
    const uint32_t kfrag0 = sK + (uint32_t)((lane & 7) * 80 + (lane >> 3) * 16);
    const uint32_t vfrag0 = sV + (uint32_t)((lane & 7) * 144 + (lane >> 3) * 16);

    float oacc[4][4];
#pragma unroll
    for (int i = 0; i < 4; i++)
#pragma unroll
        for (int j = 0; j < 4; j++) oacc[i][j] = 0.f;
    float l_lo = 0.f, l_hi = 0.f;

    for (int kb = 0; kb < NKB; kb++) {
        const int s = kb % 3;

        if (kb == NKB - 1) cp_wait0(); else cp_wait1();
        __syncthreads();

        const uint32_t kf = kfrag0 + (uint32_t)(s * KBLK * 80);
        const uint32_t vf = vfrag0 + (uint32_t)(s * HD * 144);

        // ---- GEMM1: S = Q @ K^T via ldmatrix B-frags ----
        float sacc[8][4];
#pragma unroll
        for (int nt = 0; nt < 8; nt++) {
#pragma unroll
            for (int j = 0; j < 4; j++) sacc[nt][j] = 0.f;
            unsigned b0, b1, b2, b3;
            ldsm4(b0, b1, b2, b3, kf + (uint32_t)(nt * 8 * 80));
            mma16816(sacc[nt], qa[0], b0, b1);
            mma16816(sacc[nt], qa[1], b2, b3);
        }

        // ---- exp + per-lane partial row sums ----
        unsigned pa[4][4];
#pragma unroll
        for (int nt = 0; nt < 8; nt++) {
            float p0 = ex2(sacc[nt][0]);
            float p1 = ex2(sacc[nt][1]);
            float p2 = ex2(sacc[nt][2]);
            float p3 = ex2(sacc[nt][3]);
            l_lo += p0 + p1; l_hi += p2 + p3;
            unsigned* pr = &pa[nt >> 1][(nt & 1) ? 2 : 0];
            pr[0] = pack_h2(p0, p1);
            pr[1] = pack_h2(p2, p3);
        }

        // ---- GEMM2: O += P @ V via ldmatrix B-frags ----
#pragma unroll
        for (int nt2 = 0; nt2 < 4; nt2++) {
            unsigned c0, c1, c2, c3;
            ldsm4(c0, c1, c2, c3, vf + (uint32_t)(nt2 * 8 * 144));
            mma16816(oacc[nt2], pa[0], c0, c1);
            mma16816(oacc[nt2], pa[1], c2, c3);
            ldsm4(c0, c1, c2, c3, vf + (uint32_t)(nt2 * 8 * 144 + 64));
            mma16816(oacc[nt2], pa[2], c0, c1);
            mma16816(oacc[nt2], pa[3], c2, c3);
        }

        // ---- prefetch kb+2 into stage (kb+2)%3 ----
        if (kb + 2 < NKB) {
            const int sn = (kb + 2) % 3;
            size_t off = (size_t)(kb + 2) * 64;
            cp16(kdstb + (uint32_t)(sn * KBLK * 80), ksrc + off * 32);
            cp16(vdstb + (uint32_t)(sn * HD * 144), vsrc + off);
            cp_commit();
        }
    }

    // ---- deferred row-sum reduction ----
    l_lo += __shfl_xor_sync(0xffffffffu, l_lo, 1);
    l_lo += __shfl_xor_sync(0xffffffffu, l_lo, 2);
    l_hi += __shfl_xor_sync(0xffffffffu, l_hi, 1);
    l_hi += __shfl_xor_sync(0xffffffffu, l_hi, 2);

    // ---- epilogue: normalize, add prefetched conv, store ----
    float il_lo = 1.f / l_lo;
    float il_hi = 1.f / l_hi;
    float* og = out + (size_t)b * LL * CC + head * HD;
#pragma unroll
    for (int nt2 = 0; nt2 < 4; nt2++) {
        int col = nt2 * 8 + 2 * tg;
        float2 vlo = make_float2(oacc[nt2][0] * il_lo + cpre_lo[nt2].x,
                                 oacc[nt2][1] * il_lo + cpre_lo[nt2].y);
        float2 vhi = make_float2(oacc[nt2][2] * il_hi + cpre_hi[nt2].x,
                                 oacc[nt2][3] * il_hi + cpre_hi[nt2].y);
        *(float2*)(og + (size_t)ll_lo * CC + col) = vlo;
        *(float2*)(og + (size_t)ll_hi * CC + col) = vhi;
    }
}

// ---------------- launch ----------------
extern "C" void kernel_launch(void* const* d_in, const int* in_sizes, int n_in,
                              void* d_out, int out_size) {
    const float* qkv  = nullptr;
    const float* wgt  = nullptr;
    const float* bias = nullptr;
    for (int i = 0; i < n_in; i++) {
        if (in_sizes[i] == QKV_ELEMS)       qkv  = (const float*)d_in[i];
        else if (in_sizes[i] == WGT_ELEMS)  wgt  = (const float*)d_in[i];
        else if (in_sizes[i] == BIAS_ELEMS) bias = (const float*)d_in[i];
    }
    if (!qkv)  qkv  = (const float*)d_in[0];
    if (!wgt)  wgt  = (const float*)d_in[1];
    if (!bias) bias = (const float*)d_in[2];
    float* out = (float*)d_out;

    prepass_kernel<<<1024 + 4096, 256>>>(qkv, wgt, bias);
    attn_kernel<<<128 * NHEADS * (NN / QBLK), 256>>>(qkv, out);
}

// round 16
// speedup vs baseline: 1.0512x; 1.0512x over previous
#include <cuda_runtime.h>
#include <cuda_fp16.h>
#include <math.h>
#include <stdint.h>

// ---------------- static problem config ----------------
#define BB      2
#define TT      8
#define HH      64
#define WW      64
#define CC      128
#define LL      (TT * HH * WW)      // 32768
#define NHEADS  4
#define HD      32
#define NN      512                  // tokens per window
#define QBLK    128                  // queries per CTA
#define KBLK    64                   // keys per iteration
#define NKB     (NN / KBLK)          // 8
#define SCALE_Q 0.17677669529663687f // 32^-0.5
#define LOG2E   1.4426950408889634f

#define QKV_ELEMS  (3 * BB * LL * CC)   // 25165824
#define WGT_ELEMS  (CC * 27)            // 3456
#define BIAS_ELEMS (CC)                 // 128

// fp16 scratch: [win(128)][head(4)] slabs
// Kh: [wh][n(512)][d(32)] row-major; Vh: [wh][d(32)][n(512)] (transposed)
#define WH_SLAB (512 * 32)
__device__ __half d_Kh[128 * 4 * WH_SLAB];
__device__ __half d_Vh[128 * 4 * WH_SLAB];
// LePE conv result, same layout as out (B, L, C) fp32
__device__ float d_conv[(size_t)BB * LL * CC];

// window l index: l = tB*8192 + ts*4096 + hs*64 + wB*4 + ws
__device__ __forceinline__ int l_of(int n, int tB, int wB) {
    return tB * 8192 + (n >> 8) * 4096 + ((n >> 2) & 63) * 64 + wB * 4 + (n & 3);
}

__device__ __forceinline__ void mma16816(float c[4], const unsigned a[4],
                                         unsigned b0, unsigned b1) {
    asm volatile(
        "mma.sync.aligned.m16n8k16.row.col.f32.f16.f16.f32 "
        "{%0,%1,%2,%3},{%4,%5,%6,%7},{%8,%9},{%0,%1,%2,%3};\n"
        : "+f"(c[0]), "+f"(c[1]), "+f"(c[2]), "+f"(c[3])
        : "r"(a[0]), "r"(a[1]), "r"(a[2]), "r"(a[3]), "r"(b0), "r"(b1));
}

__device__ __forceinline__ void ldsm4(unsigned& r0, unsigned& r1,
                                      unsigned& r2, unsigned& r3, uint32_t addr) {
    asm volatile(
        "ldmatrix.sync.aligned.m8n8.x4.shared.b16 {%0,%1,%2,%3}, [%4];\n"
        : "=r"(r0), "=r"(r1), "=r"(r2), "=r"(r3) : "r"(addr));
}

__device__ __forceinline__ unsigned pack_h2(float lo, float hi) {
    __half2 h = __floats2half2_rn(lo, hi);
    return *reinterpret_cast<unsigned*>(&h);
}

__device__ __forceinline__ float ex2(float x) {
    float y;
    asm("ex2.approx.f32 %0, %1;" : "=f"(y) : "f"(x));
    return y;
}

__device__ __forceinline__ void cp16(uint32_t dst, const void* src) {
    asm volatile("cp.async.cg.shared.global [%0], [%1], 16;\n" :: "r"(dst), "l"(src));
}
__device__ __forceinline__ void cp_commit() {
    asm volatile("cp.async.commit_group;\n" ::: "memory");
}
__device__ __forceinline__ void cp_wait1() {
    asm volatile("cp.async.wait_group 1;\n" ::: "memory");
}
__device__ __forceinline__ void cp_wait0() {
    asm volatile("cp.async.wait_group 0;\n" ::: "memory");
}

// ---------------- prepass: K,V fp32 -> fp16 window-major scratch ----------------
// V: thread = (wh, nchunk, d); lanes sweep d -> coalesced reads AND coalesced
// transposed uint4 store (kills the old 2B/1KB-stride write scatter).
// K: first 2048 blocks also each convert one 16-half row chunk (coalesced).
__global__ __launch_bounds__(256)
void reorg_kernel(const float* __restrict__ qkv) {
    const int gid = blockIdx.x * 256 + threadIdx.x;
    const size_t plane = (size_t)BB * LL * CC;

    // ---- V item: one (wh, d, 8 keys) -> uint4 store ----
    {
        int d      = gid & 31;
        int nchunk = (gid >> 5) & 63;
        int wh     = gid >> 11;           // 0..511
        int win    = wh >> 2;
        int head   = wh & 3;
        int b  = win >> 6;
        int tB = (win >> 4) & 3;
        int wB = win & 15;

        int n0 = nchunk * 8;
        const float* vp = qkv + 2 * plane + (size_t)b * LL * CC + head * HD + d;
        uint4 uv;
        __half2 h01, h23, h45, h67;
        {
            float f0 = vp[(size_t)l_of(n0 + 0, tB, wB) * CC];
            float f1 = vp[(size_t)l_of(n0 + 1, tB, wB) * CC];
            float f2 = vp[(size_t)l_of(n0 + 2, tB, wB) * CC];
            float f3 = vp[(size_t)l_of(n0 + 3, tB, wB) * CC];
            float f4 = vp[(size_t)l_of(n0 + 4, tB, wB) * CC];
            float f5 = vp[(size_t)l_of(n0 + 5, tB, wB) * CC];
            float f6 = vp[(size_t)l_of(n0 + 6, tB, wB) * CC];
            float f7 = vp[(size_t)l_of(n0 + 7, tB, wB) * CC];
            h01 = __floats2half2_rn(f0, f1);
            h23 = __floats2half2_rn(f2, f3);
            h45 = __floats2half2_rn(f4, f5);
            h67 = __floats2half2_rn(f6, f7);
        }
        ((__half2*)&uv)[0] = h01;
        ((__half2*)&uv)[1] = h23;
        ((__half2*)&uv)[2] = h45;
        ((__half2*)&uv)[3] = h67;
        *(uint4*)(d_Vh + (size_t)wh * WH_SLAB + (size_t)d * 512 + n0) = uv;
    }

    // ---- K item: one (wh, n, 16-half chunk) ----
    if (gid < 512 * 512 * 2) {
        int c  = gid & 1;
        int n  = (gid >> 1) & 511;
        int wh = gid >> 10;               // 0..511
        int win  = wh >> 2;
        int head = wh & 3;
        int b  = win >> 6;
        int tB = (win >> 4) & 3;
        int wB = win & 15;
        int l  = l_of(n, tB, wB);

        const float* kp = qkv + plane + ((size_t)b * LL + l) * CC + head * HD + c * 16;
        float4 k0 = ((const float4*)kp)[0];
        float4 k1 = ((const float4*)kp)[1];
        float4 k2 = ((const float4*)kp)[2];
        float4 k3 = ((const float4*)kp)[3];
        uint4 ua, ub;
        ((__half2*)&ua)[0] = __floats2half2_rn(k0.x, k0.y);
        ((__half2*)&ua)[1] = __floats2half2_rn(k0.z, k0.w);
        ((__half2*)&ua)[2] = __floats2half2_rn(k1.x, k1.y);
        ((__half2*)&ua)[3] = __floats2half2_rn(k1.z, k1.w);
        ((__half2*)&ub)[0] = __floats2half2_rn(k2.x, k2.y);
        ((__half2*)&ub)[1] = __floats2half2_rn(k2.z, k2.w);
        ((__half2*)&ub)[2] = __floats2half2_rn(k3.x, k3.y);
        ((__half2*)&ub)[3] = __floats2half2_rn(k3.z, k3.w);
        __half* kd = d_Kh + (size_t)wh * WH_SLAB + (size_t)n * 32 + c * 16;
        ((uint4*)kd)[0] = ua;
        ((uint4*)kd)[1] = ub;
    }
}

// ---------------- LePE depthwise 3x3x3 conv -> d_conv (write-only) ----------------
__global__ __launch_bounds__(256, 2)
void lepe_kernel(const float* __restrict__ qkv, const float* __restrict__ wgt,
                 const float* __restrict__ bias) {
    __shared__ __align__(16) float slab[NN * 16];
    __shared__ __align__(16) float wt[27][16];
    __shared__ __align__(16) float bs[16];

    const int widx  = blockIdx.x >> 3;
    const int chunk = blockIdx.x & 7;
    const int c0    = chunk * 16;
    const int b  = widx >> 6;
    const int tB = (widx >> 4) & 3;
    const int wB = widx & 15;
    const int tid = threadIdx.x;

    const float* vg = qkv + 2 * (size_t)BB * LL * CC + (size_t)b * LL * CC + c0;

    for (int t = tid; t < NN * 4; t += 256) {
        int n = t >> 2, cgq = t & 3;
        int l = l_of(n, tB, wB);
        float4 f = *(const float4*)(vg + (size_t)l * CC + cgq * 4);
        *(float4*)&slab[n * 16 + cgq * 4] = f;
    }
    for (int t = tid; t < 27 * 16; t += 256) {
        int tap = t >> 4, ci = t & 15;
        wt[tap][ci] = wgt[(size_t)(c0 + ci) * 27 + tap];
    }
    if (tid < 16) bs[tid] = bias[c0 + tid];
    __syncthreads();

    const int cg     = tid & 3;
    const int ws     = (tid >> 2) & 3;
    const int hstrip = (tid >> 4) & 15;
    const int hs0    = hstrip * 4;
    float4 bias4 = *(float4*)&bs[cg * 4];
    float* og = d_conv + (size_t)b * LL * CC + c0;

#pragma unroll
    for (int ts = 0; ts < 2; ts++) {
        float4 acc[4];
#pragma unroll
        for (int j = 0; j < 4; j++) acc[j] = bias4;

#pragma unroll
        for (int zt = 0; zt < 2; zt++) {
            const int dt1 = zt - ts + 1;
#pragma unroll
            for (int dw = -1; dw <= 1; dw++) {
                int zw = ws + dw;
                if ((unsigned)zw >= 4u) continue;
                float4 wm = *(float4*)&wt[dt1 * 9 + 0 * 3 + (dw + 1)][cg * 4];
                float4 wz = *(float4*)&wt[dt1 * 9 + 1 * 3 + (dw + 1)][cg * 4];
                float4 wp = *(float4*)&wt[dt1 * 9 + 2 * 3 + (dw + 1)][cg * 4];
#pragma unroll
                for (int u = 0; u < 6; u++) {
                    int zh = hs0 - 1 + u;
                    if ((unsigned)zh >= 64u) continue;
                    float4 v = *(float4*)&slab[(zt * 256 + zh * 4 + zw) * 16 + cg * 4];
                    if (u <= 3) {
                        acc[u].x += v.x * wm.x; acc[u].y += v.y * wm.y;
                        acc[u].z += v.z * wm.z; acc[u].w += v.w * wm.w;
                    }
                    if (u >= 1 && u <= 4) {
                        acc[u-1].x += v.x * wz.x; acc[u-1].y += v.y * wz.y;
                        acc[u-1].z += v.z * wz.z; acc[u-1].w += v.w * wz.w;
                    }
                    if (u >= 2) {
                        acc[u-2].x += v.x * wp.x; acc[u-2].y += v.y * wp.y;
                        acc[u-2].z += v.z * wp.z; acc[u-2].w += v.w * wp.w;
                    }
                }
            }
        }

#pragma unroll
        for (int j = 0; j < 4; j++) {
            int n = ts * 256 + (hs0 + j) * 4 + ws;
            int l = l_of(n, tB, wB);
            *(float4*)(og + (size_t)l * CC + cg * 4) = acc[j];
        }
    }
}

// ---------------- attention kernel: LDSM fragments + 3-stage cp.async ----------------
// grid = 2048 CTAs, 256 threads (8 warps x 16 q rows). Epilogue adds d_conv (prefetched).
__global__ __launch_bounds__(256, 2)
void attn_kernel(const float* __restrict__ qkv, float* __restrict__ out) {
    __shared__ __align__(16) __half Qs[QBLK][40];
    __shared__ __align__(16) __half Ks[3][KBLK][40];     // row stride 80B
    __shared__ __align__(16) __half Vt[3][HD][KBLK + 8]; // row stride 144B

    const int bid  = blockIdx.x;
    const int qb   = bid & 3;
    const int head = (bid >> 2) & 3;
    const int win  = bid >> 4;
    const int b    = win >> 6;
    const int tB   = (win >> 4) & 3;
    const int wB   = win & 15;

    const int tid  = threadIdx.x;
    const int warp = tid >> 5;
    const int lane = tid & 31;
    const int g    = lane >> 2;
    const int tg   = lane & 3;

    size_t wh = (size_t)(win * 4 + head);
    const __half* Kg = d_Kh + wh * WH_SLAB;
    const __half* Vg = d_Vh + wh * WH_SLAB;

    const uint32_t sK = (uint32_t)__cvta_generic_to_shared(&Ks[0][0][0]);
    const uint32_t sV = (uint32_t)__cvta_generic_to_shared(&Vt[0][0][0]);

    const int krow = tid >> 2, kpart = tid & 3;
    const int vrow = tid >> 3, vpart = tid & 7;
    const uint32_t kdstb = sK + (uint32_t)(krow * 80 + kpart * 16);
    const uint32_t vdstb = sV + (uint32_t)(vrow * 144 + vpart * 16);
    const __half* ksrc = Kg + (size_t)krow * 32 + kpart * 8;
    const __half* vsrc = Vg + (size_t)vrow * 512 + vpart * 8;

    // ---- prologue: issue kv stage0, stage1 ----
    cp16(kdstb, ksrc);
    cp16(vdstb, vsrc);
    cp_commit();
    cp16(kdstb + KBLK * 80, ksrc + 64 * 32);
    cp16(vdstb + HD * 144, vsrc + 64);
    cp_commit();

    // ---- epilogue indices + conv prefetch into registers (hidden by mainloop) ----
    const int rb = warp * 16;
    int n_lo = qb * QBLK + rb + g;
    int ll_lo = l_of(n_lo, tB, wB);
    int ll_hi = l_of(n_lo + 8, tB, wB);
    const float* cvg = d_conv + (size_t)b * LL * CC + head * HD;
    float2 cpre_lo[4], cpre_hi[4];
#pragma unroll
    for (int nt2 = 0; nt2 < 4; nt2++) {
        int col = nt2 * 8 + 2 * tg;
        cpre_lo[nt2] = *(const float2*)(cvg + (size_t)ll_lo * CC + col);
        cpre_hi[nt2] = *(const float2*)(cvg + (size_t)ll_hi * CC + col);
    }

    // ---- Q: fp32 direct load + scale + convert (overlaps with cp.async) ----
    const float QS = SCALE_Q * LOG2E;
    const float* qg = qkv + (size_t)b * LL * CC + head * HD;
    for (int t = tid; t < QBLK * 8; t += 256) {
        int r = t >> 3, d4 = (t & 7) * 4;
        int n = qb * QBLK + r;
        int l = l_of(n, tB, wB);
        float4 f = *(const float4*)(qg + (size_t)l * CC + d4);
        *(__half2*)&Qs[r][d4]     = __floats2half2_rn(f.x * QS, f.y * QS);
        *(__half2*)&Qs[r][d4 + 2] = __floats2half2_rn(f.z * QS, f.w * QS);
    }
    __syncthreads();

    unsigned qa[2][4];
#pragma unroll
    for (int kk = 0; kk < 2; kk++) {
        qa[kk][0] = *(const unsigned*)&Qs[rb + g][kk * 16 + 2 * tg];
        qa[kk][1] = *(const unsigned*)&Qs[rb + g + 8][kk * 16 + 2 * tg];
        qa[kk][2] = *(const unsigned*)&Qs[rb + g][kk * 16 + 2 * tg + 8];
        qa[kk][3] = *(const unsigned*)&Qs[rb + g + 8][kk * 16 + 2 * tg + 8];
    }

    // ldmatrix lane addresses (stage 0 base): 8 rows per tile, 4 k/n-chunks
    const uint32_t kfrag0 = sK + (uint32_t)((lane & 7) * 80 + (lane >> 3) * 16);
    const uint32_t vfrag0 = sV + (uint32_t)((lane & 7) * 144 + (lane >> 3) * 16);

    float oacc[4][4];
#pragma unroll
    for (int i = 0; i < 4; i++)
#pragma unroll
        for (int j = 0; j < 4; j++) oacc[i][j] = 0.f;
    float l_lo = 0.f, l_hi = 0.f;

    for (int kb = 0; kb < NKB; kb++) {
        const int s = kb % 3;

        if (kb == NKB - 1) cp_wait0(); else cp_wait1();
        __syncthreads();

        const uint32_t kf = kfrag0 + (uint32_t)(s * KBLK * 80);
        const uint32_t vf = vfrag0 + (uint32_t)(s * HD * 144);

        // ---- GEMM1: S = Q @ K^T via ldmatrix B-frags ----
        float sacc[8][4];
#pragma unroll
        for (int nt = 0; nt < 8; nt++) {
#pragma unroll
            for (int j = 0; j < 4; j++) sacc[nt][j] = 0.f;
            unsigned b0, b1, b2, b3;
            ldsm4(b0, b1, b2, b3, kf + (uint32_t)(nt * 8 * 80));
            mma16816(sacc[nt], qa[0], b0, b1);
            mma16816(sacc[nt], qa[1], b2, b3);
        }

        // ---- exp + per-lane partial row sums ----
        unsigned pa[4][4];
#pragma unroll
        for (int nt = 0; nt < 8; nt++) {
            float p0 = ex2(sacc[nt][0]);
            float p1 = ex2(sacc[nt][1]);
            float p2 = ex2(sacc[nt][2]);
            float p3 = ex2(sacc[nt][3]);
            l_lo += p0 + p1; l_hi += p2 + p3;
            unsigned* pr = &pa[nt >> 1][(nt & 1) ? 2 : 0];
            pr[0] = pack_h2(p0, p1);
            pr[1] = pack_h2(p2, p3);
        }

        // ---- GEMM2: O += P @ V via ldmatrix B-frags ----
#pragma unroll
        for (int nt2 = 0; nt2 < 4; nt2++) {
            unsigned c0, c1, c2, c3;
            ldsm4(c0, c1, c2, c3, vf + (uint32_t)(nt2 * 8 * 144));
            mma16816(oacc[nt2], pa[0], c0, c1);
            mma16816(oacc[nt2], pa[1], c2, c3);
            ldsm4(c0, c1, c2, c3, vf + (uint32_t)(nt2 * 8 * 144 + 64));
            mma16816(oacc[nt2], pa[2], c0, c1);
            mma16816(oacc[nt2], pa[3], c2, c3);
        }

        // ---- prefetch kb+2 into stage (kb+2)%3 ----
        if (kb + 2 < NKB) {
            const int sn = (kb + 2) % 3;
            size_t off = (size_t)(kb + 2) * 64;
            cp16(kdstb + (uint32_t)(sn * KBLK * 80), ksrc + off * 32);
            cp16(vdstb + (uint32_t)(sn * HD * 144), vsrc + off);
            cp_commit();
        }
    }

    // ---- deferred row-sum reduction ----
    l_lo += __shfl_xor_sync(0xffffffffu, l_lo, 1);
    l_lo += __shfl_xor_sync(0xffffffffu, l_lo, 2);
    l_hi += __shfl_xor_sync(0xffffffffu, l_hi, 1);
    l_hi += __shfl_xor_sync(0xffffffffu, l_hi, 2);

    // ---- epilogue: normalize, add prefetched conv, store ----
    float il_lo = 1.f / l_lo;
    float il_hi = 1.f / l_hi;
    float* og = out + (size_t)b * LL * CC + head * HD;
#pragma unroll
    for (int nt2 = 0; nt2 < 4; nt2++) {
        int col = nt2 * 8 + 2 * tg;
        float2 vlo = make_float2(oacc[nt2][0] * il_lo + cpre_lo[nt2].x,
                                 oacc[nt2][1] * il_lo + cpre_lo[nt2].y);
        float2 vhi = make_float2(oacc[nt2][2] * il_hi + cpre_hi[nt2].x,
                                 oacc[nt2][3] * il_hi + cpre_hi[nt2].y);
        *(float2*)(og + (size_t)ll_lo * CC + col) = vlo;
        *(float2*)(og + (size_t)ll_hi * CC + col) = vhi;
    }
}

// ---------------- launch ----------------
extern "C" void kernel_launch(void* const* d_in, const int* in_sizes, int n_in,
                              void* d_out, int out_size) {
    const float* qkv  = nullptr;
    const float* wgt  = nullptr;
    const float* bias = nullptr;
    for (int i = 0; i < n_in; i++) {
        if (in_sizes[i] == QKV_ELEMS)       qkv  = (const float*)d_in[i];
        else if (in_sizes[i] == WGT_ELEMS)  wgt  = (const float*)d_in[i];
        else if (in_sizes[i] == BIAS_ELEMS) bias = (const float*)d_in[i];
    }
    if (!qkv)  qkv  = (const float*)d_in[0];
    if (!wgt)  wgt  = (const float*)d_in[1];
    if (!bias) bias = (const float*)d_in[2];
    float* out = (float*)d_out;

    reorg_kernel<<<4096, 256>>>(qkv);
    lepe_kernel<<<128 * 8, 256>>>(qkv, wgt, bias);
    attn_kernel<<<128 * NHEADS * (NN / QBLK), 256>>>(qkv, out);
}